// round 15
// baseline (speedup 1.0000x reference)
#include <cuda_runtime.h>
#include <cuda_fp16.h>
#include <math.h>

typedef unsigned long long ull;
typedef unsigned int u32;

#define NB   16384
#define DD   512
#define NE   8
#define NH1  1024
#define NH2  512
#define TT1  256
#define TT2  128
#define PEN  5
#define KAIT 2560   // D*PE

// ---- output layout ----
#define O0 ((size_t)0)
#define O1 ((size_t)NB)
#define O2 ((size_t)2*NB)
#define O3 ((size_t)3*NB)
#define O4 (O3 + (size_t)NB*512)
#define O5 (O4 + (size_t)NB*512)
#define O6 (O5 + (size_t)NB*512)
#define O7 (O6 + (size_t)NB*128)
#define O8 (O7 + (size_t)NB*128)

// ---- scratch ----
__device__ __half g_xh [(size_t)NB*DD];
__device__ __half g_cxh[(size_t)NB*1024];   // [x | pctr*x] hi only
__device__ __half g_Hh [(size_t)NE*NB*NH1];
__device__ __half g_FEAh[(size_t)NE*NB*NH2];
__device__ __half g_W1h[(size_t)NE*NH1*DD];
__device__ __half g_W2h[(size_t)NE*NH2*NH1];
__device__ __half g_CUh[(size_t)NE*NH1*1024];  // [U0;U1] per expert, [N][1024]
__device__ __half g_CW2h[(size_t)NE*NH2*NH1];
__device__ __half g_tW1h[(size_t)2*TT1*NH2];
__device__ __half g_tW2h[(size_t)2*TT2*TT1];
__device__ __half g_cW1h[(size_t)TT1*NH2];
__device__ __half g_cW2h[(size_t)TT2*TT1];
__device__ __half g_tfh[(size_t)2*NB*NH2];
__device__ __half g_th1h[(size_t)2*NB*TT1];
__device__ __half g_cth[(size_t)NB*NH2];
__device__ __half g_ch1h[(size_t)NB*TT1];
__device__ float g_GATES[(size_t)NB*2*8];
__device__ float g_CGATE[(size_t)NB*8];
__device__ float g_UG  [(size_t)2*DD*8];    // cgate u0/u1

// ================= helpers =================
__device__ __forceinline__ u32 smem_u32(const void* p) {
    u32 a;
    asm("{ .reg .u64 t; cvta.to.shared.u64 t, %1; cvt.u32.u64 %0, t; }" : "=r"(a) : "l"(p));
    return a;
}
__device__ __forceinline__ void cpa16(u32 dst, const void* src) {
    asm volatile("cp.async.cg.shared.global [%0], [%1], 16;" :: "r"(dst), "l"(src) : "memory");
}
#define CPA_COMMIT() asm volatile("cp.async.commit_group;" ::: "memory")
#define CPA_WAIT1()  asm volatile("cp.async.wait_group 1;" ::: "memory")

__device__ __forceinline__ void mma16816(float* c, const u32* a, const u32* b) {
    asm volatile(
        "mma.sync.aligned.m16n8k16.row.col.f32.f16.f16.f32 "
        "{%0,%1,%2,%3}, {%4,%5,%6,%7}, {%8,%9}, {%0,%1,%2,%3};"
        : "+f"(c[0]), "+f"(c[1]), "+f"(c[2]), "+f"(c[3])
        : "r"(a[0]), "r"(a[1]), "r"(a[2]), "r"(a[3]), "r"(b[0]), "r"(b[1]));
}

// swizzled smem offset (64B rows, 4x16B chunks)
__device__ __forceinline__ u32 swz(int row, int ch) {
    return (u32)(row * 64 + ((ch ^ ((row >> 1) & 3)) << 4));
}

__device__ __forceinline__ void ldA(u32 tb, int row0, int s, u32* a) {
    int lane = threadIdx.x & 31;
    int g = lane >> 3, li = lane & 7;
    int row = row0 + ((g & 1) << 3) + li;
    int ch = 2 * s + (g >> 1);
    u32 addr = tb + swz(row, ch);
    asm volatile("ldmatrix.sync.aligned.m8n8.x4.shared.b16 {%0,%1,%2,%3}, [%4];"
        : "=r"(a[0]), "=r"(a[1]), "=r"(a[2]), "=r"(a[3]) : "r"(addr));
}
__device__ __forceinline__ void ldB(u32 tb, int n0, int s, u32* r) {
    int lane = threadIdx.x & 31;
    int g = lane >> 3, li = lane & 7;
    int row = n0 + ((g >> 1) << 3) + li;
    int ch = 2 * s + (g & 1);
    u32 addr = tb + swz(row, ch);
    asm volatile("ldmatrix.sync.aligned.m8n8.x4.shared.b16 {%0,%1,%2,%3}, [%4];"
        : "=r"(r[0]), "=r"(r[1]), "=r"(r[2]), "=r"(r[3]) : "r"(addr));
}

// ============================================================
// HMMA GEMM, one-pass, k=64 chunks, 3-stage cp.async pipeline.
//   C[z] = relu(A[z] @ B[z]^T + bias[z])
// A [M, aK] fp16; B [N, K] fp16 (pre-transposed).
// A k-col for 32-chunk c32 = (c32 & acolmask)*32.  K % 64 == 0, K >= 128.
// 96KB smem -> 2 CTAs/SM.
// mode: 0 = fp32 C, 2 = fp16 C.
// ============================================================
__global__ void __launch_bounds__(256, 2) hmma_t(
    const __half* __restrict__ Ah,
    const __half* __restrict__ Bh, const float* __restrict__ bias,
    float* __restrict__ Cf, __half* __restrict__ Ch,
    int N, int K, int acolmask, int aK,
    size_t sA, size_t sB, size_t sBias, size_t sC, int mode)
{
    extern __shared__ char dsm[];
    const int SUB   = 16384;
    const int STAGE = 2 * SUB;
    const int NSLOT = 4;
    const int tid = threadIdx.x;
    const int wid = tid >> 5;
    const int lane = tid & 31;
    const int z = blockIdx.z;
    const int bm = blockIdx.y << 7;
    const int bn = blockIdx.x << 7;

    Ah += (size_t)z * sA;
    Bh += (size_t)z * sB;  bias += (size_t)z * sBias;

    const u32 sbase = smem_u32(dsm);

    u32 soff[NSLOT];
    const __half* gsrc[NSLOT];
    u32 amask[NSLOT];
    #pragma unroll
    for (int j = 0; j < NSLOT; j++) {
        int sid = tid + (j << 8);
        int buf = sid >> 9;
        int rem = sid & 511;
        int r = rem >> 2;
        int ch = rem & 3;
        soff[j] = (u32)(buf * 8192) + swz(r, ch);
        bool isA = (buf == 0);
        const __half* base = isA ? Ah : Bh;
        int grow = (isA ? bm : bn) + r;
        gsrc[j] = base + (size_t)grow * (isA ? aK : K) + ch * 8;
        amask[j] = isA ? (u32)acolmask : 0xFFFFFFFFu;
    }

    const int nch = K >> 6;   // 64-k chunks

    // prologue: fill stages 0,1
    #pragma unroll
    for (int p = 0; p < 2; p++) {
        u32 sb = sbase + (u32)p * STAGE;
        #pragma unroll
        for (int sc = 0; sc < 2; sc++)
            #pragma unroll
            for (int j = 0; j < NSLOT; j++)
                cpa16(sb + (u32)sc * SUB + soff[j],
                      gsrc[j] + (((u32)(2 * p + sc) & amask[j]) << 5));
        CPA_COMMIT();
    }

    const int wm = (wid & 3) << 5;
    const int wn = (wid >> 2) << 6;
    const u32 Boff = 8192u;

    float acc[2][8][4];
    #pragma unroll
    for (int i = 0; i < 2; i++)
        #pragma unroll
        for (int j = 0; j < 8; j++)
            #pragma unroll
            for (int q = 0; q < 4; q++) acc[i][j][q] = 0.f;

    int stg = 0;   // i % 3
    for (int i = 0; i < nch; i++) {
        CPA_WAIT1();
        __syncthreads();
        int pf = i + 2;
        if (pf < nch) {
            int pstg = stg + 2; if (pstg >= 3) pstg -= 3;
            u32 sb = sbase + (u32)pstg * STAGE;
            #pragma unroll
            for (int sc = 0; sc < 2; sc++)
                #pragma unroll
                for (int j = 0; j < NSLOT; j++)
                    cpa16(sb + (u32)sc * SUB + soff[j],
                          gsrc[j] + (((u32)(2 * pf + sc) & amask[j]) << 5));
        }
        CPA_COMMIT();

        #pragma unroll
        for (int sc = 0; sc < 2; sc++) {
            u32 stb = sbase + (u32)stg * STAGE + (u32)sc * SUB;
            #pragma unroll
            for (int s = 0; s < 2; s++) {
                u32 ah[2][4], b[8][2];
                ldA(stb, wm,      s, ah[0]);
                ldA(stb, wm + 16, s, ah[1]);
                #pragma unroll
                for (int j4 = 0; j4 < 4; j4++) {
                    u32 r[4];
                    ldB(stb + Boff, wn + j4 * 16, s, r);
                    b[2 * j4][0] = r[0]; b[2 * j4][1] = r[1];
                    b[2 * j4 + 1][0] = r[2]; b[2 * j4 + 1][1] = r[3];
                }
                #pragma unroll
                for (int i2 = 0; i2 < 2; i2++)
                    #pragma unroll
                    for (int j8 = 0; j8 < 8; j8++) mma16816(acc[i2][j8], ah[i2], b[j8]);
            }
        }
        if (++stg == 3) stg = 0;
    }

    // epilogue
    const int r0b = bm + wm + (lane >> 2);
    const int c0b = bn + wn + ((lane & 3) << 1);
    #pragma unroll
    for (int i2 = 0; i2 < 2; i2++) {
        #pragma unroll
        for (int j8 = 0; j8 < 8; j8++) {
            int col = c0b + j8 * 8;
            float b0 = bias[col], b1 = bias[col + 1];
            #pragma unroll
            for (int h = 0; h < 2; h++) {
                int row = r0b + i2 * 16 + h * 8;
                float v0 = fmaxf(acc[i2][j8][2 * h]     + b0, 0.f);
                float v1 = fmaxf(acc[i2][j8][2 * h + 1] + b1, 0.f);
                if (mode == 0) {
                    *(float2*)(Cf + (size_t)z * sC + (size_t)row * N + col) = make_float2(v0, v1);
                } else {
                    __half2 hp;
                    hp.x = __float2half_rn(v0);
                    hp.y = __float2half_rn(v1);
                    *(__half2*)(Ch + (size_t)z * sC + (size_t)row * N + col) = hp;
                }
            }
        }
    }
}

// ============================================================
// weight transpose: W[z][K][N] f32 -> T[z][N][K] fp16
// ============================================================
__global__ void transpose_h(const float* __restrict__ W, __half* __restrict__ Th,
                            int Kd, int Nd)
{
    __shared__ float t[32][33];
    int z = blockIdx.z;
    const float* Wz = W + (size_t)z * Kd * Nd;
    int n0 = blockIdx.x << 5, k0 = blockIdx.y << 5;
    for (int r = threadIdx.y; r < 32; r += 8)
        t[r][threadIdx.x] = Wz[(size_t)(k0 + r) * Nd + n0 + threadIdx.x];
    __syncthreads();
    size_t ob = (size_t)z * Nd * Kd;
    for (int r = threadIdx.y; r < 32; r += 8)
        Th[ob + (size_t)(n0 + r) * Kd + k0 + threadIdx.x] = __float2half_rn(t[threadIdx.x][r]);
}

// CE1 collapse: ceW1[z][d*5+p][n] f32 -> CU[z][n][d] = sum_p embB_p*W,
//                                        CU[z][n][512+d] = sum_p embW_p*W
__global__ void prep_cu(const float* __restrict__ W, const float* __restrict__ embW,
                        const float* __restrict__ embB, __half* __restrict__ CU)
{
    __shared__ float t0[32][33], t1[32][33];
    int z = blockIdx.z;
    int n0 = blockIdx.x << 5, d0 = blockIdx.y << 5;
    const float* Wz = W + (size_t)z * KAIT * NH1;
    float ew[PEN], eb[PEN];
    #pragma unroll
    for (int p = 0; p < PEN; p++) { ew[p] = embW[p]; eb[p] = embB[p]; }
    for (int r = threadIdx.y; r < 32; r += 8) {
        float s0 = 0.f, s1 = 0.f;
        #pragma unroll
        for (int p = 0; p < PEN; p++) {
            float w = Wz[(size_t)((d0 + r) * PEN + p) * NH1 + n0 + threadIdx.x];
            s0 += eb[p] * w;
            s1 += ew[p] * w;
        }
        t0[r][threadIdx.x] = s0;
        t1[r][threadIdx.x] = s1;
    }
    __syncthreads();
    size_t ob = (size_t)z * NH1 * 1024;
    for (int r = threadIdx.y; r < 32; r += 8) {
        CU[ob + (size_t)(n0 + r) * 1024 + d0 + threadIdx.x] =
            __float2half_rn(t0[threadIdx.x][r]);
        CU[ob + (size_t)(n0 + r) * 1024 + 512 + d0 + threadIdx.x] =
            __float2half_rn(t1[threadIdx.x][r]);
    }
}

// cgate collapse: u0[d][e] = sum_p embB_p*cgW[d*5+p][e]; u1 likewise with embW
__global__ void prep_ug(const float* __restrict__ cgW, const float* __restrict__ embW,
                        const float* __restrict__ embB, float* __restrict__ u)
{
    int i = blockIdx.x * blockDim.x + threadIdx.x;
    if (i >= DD * 8) return;
    int d = i >> 3, e = i & 7;
    float s0 = 0.f, s1 = 0.f;
    #pragma unroll
    for (int p = 0; p < PEN; p++) {
        float w = cgW[(size_t)(d * PEN + p) * 8 + e];
        s0 += embB[p] * w;
        s1 += embW[p] * w;
    }
    u[i] = s0;
    u[DD * 8 + i] = s1;
}

// elementwise fp32 -> fp16 (hi only)
__global__ void convert_h(const float* __restrict__ src, __half* __restrict__ hi, size_t n)
{
    size_t i = ((size_t)blockIdx.x * blockDim.x + threadIdx.x) * 4;
    if (i >= n) return;
    float4 v = *(const float4*)(src + i);
    __half2 a, b;
    a.x = __float2half_rn(v.x); a.y = __float2half_rn(v.y);
    b.x = __float2half_rn(v.z); b.y = __float2half_rn(v.w);
    *(__half2*)(hi + i) = a; *(__half2*)(hi + i + 2) = b;
}

// ================= small fp32 kernels =================
__global__ void gates_kernel(const float* __restrict__ x, const float* __restrict__ gW,
                             const float* __restrict__ gb, float* __restrict__ gates)
{
    int gw = (blockIdx.x * blockDim.x + threadIdx.x) >> 5;
    int lane = threadIdx.x & 31;
    if (gw >= NB * 2) return;
    int b = gw >> 1, t = gw & 1;
    const float* xr = x + (size_t)b * DD;
    float acc[8] = {};
    for (int d = lane; d < DD; d += 32) {
        float xv = xr[d];
        const float* g = gW + ((size_t)t * DD + d) * NE;
        float4 w0 = *(const float4*)g;
        float4 w1 = *(const float4*)(g + 4);
        acc[0] += xv * w0.x; acc[1] += xv * w0.y; acc[2] += xv * w0.z; acc[3] += xv * w0.w;
        acc[4] += xv * w1.x; acc[5] += xv * w1.y; acc[6] += xv * w1.z; acc[7] += xv * w1.w;
    }
    #pragma unroll
    for (int e = 0; e < 8; e++)
        #pragma unroll
        for (int o = 16; o; o >>= 1) acc[e] += __shfl_xor_sync(0xffffffffu, acc[e], o);
    float m = -1e30f;
    #pragma unroll
    for (int e = 0; e < 8; e++) { acc[e] += gb[t * 8 + e]; m = fmaxf(m, acc[e]); }
    float s = 0.f;
    #pragma unroll
    for (int e = 0; e < 8; e++) { acc[e] = expf(acc[e] - m); s += acc[e]; }
    float inv = 1.f / s;
    if (lane < 8) gates[((size_t)b * 2 + t) * 8 + lane] = acc[lane] * inv;
}

// fused combine for both tasks + fp16 task_fea (tower input); FEA is fp16
__global__ void combine12(const __half* __restrict__ fea, const float* __restrict__ gates,
                          float* __restrict__ o3, float* __restrict__ o4,
                          __half* __restrict__ tfh)
{
    int b = blockIdx.x;
    __shared__ float g[16];
    if (threadIdx.x < 16) g[threadIdx.x] = gates[(size_t)b * 16 + threadIdx.x];
    __syncthreads();
    const __half* f = fea + (size_t)b * NH2;
    for (int h = threadIdx.x; h < NH2; h += blockDim.x) {
        float s0 = 0.f, s1 = 0.f;
        #pragma unroll
        for (int e = 0; e < 8; e++) {
            float v = __half2float(f[(size_t)e * NB * NH2 + h]);
            s0 += g[e] * v;
            s1 += g[8 + e] * v;
        }
        o3[(size_t)b * NH2 + h] = s0;
        o4[(size_t)b * NH2 + h] = s1;
        tfh[(size_t)b * NH2 + h] = __float2half_rn(s0);
        tfh[(size_t)(NB + b) * NH2 + h] = __float2half_rn(s1);
    }
}

// phase-2 combine: ctask -> O5 + fp16 for cascade tower; FEA is fp16
__global__ void combine1c(const __half* __restrict__ fea, const float* __restrict__ cg,
                          float* __restrict__ o5, __half* __restrict__ cth)
{
    int b = blockIdx.x;
    __shared__ float g[8];
    if (threadIdx.x < 8) g[threadIdx.x] = cg[(size_t)b * 8 + threadIdx.x];
    __syncthreads();
    const __half* f = fea + (size_t)b * NH2;
    for (int h = threadIdx.x; h < NH2; h += blockDim.x) {
        float s = 0.f;
        #pragma unroll
        for (int e = 0; e < 8; e++) s += g[e] * __half2float(f[(size_t)e * NB * NH2 + h]);
        o5[(size_t)b * NH2 + h] = s;
        cth[(size_t)b * NH2 + h] = __float2half_rn(s);
    }
}

// fused preds + cx: warps 0/1 compute pctr/pcvr, then all threads write cxh
__global__ void preds_cx_kernel(const float* __restrict__ x, const float* __restrict__ outr,
                                const float* __restrict__ pW, const float* __restrict__ pb,
                                float* __restrict__ out, __half* __restrict__ cxh)
{
    int b = blockIdx.x;
    int tid = threadIdx.x;
    int wid = tid >> 5, lane = tid & 31;
    __shared__ float spc;

    if (wid < 2) {
        int t = wid;
        const float* th2 = outr + O6 + (size_t)t * NB * TT2 + (size_t)b * TT2;
        const float* w = pW + t * TT2;
        float s = 0.f;
        for (int m = lane; m < TT2; m += 32) s += th2[m] * w[m];
        #pragma unroll
        for (int o = 16; o; o >>= 1) s += __shfl_xor_sync(0xffffffffu, s, o);
        if (lane == 0) {
            s += pb[t];
            float p = 1.f / (1.f + expf(-s));
            out[(size_t)t * NB + b] = p;
            if (t == 0) spc = p;
        }
    }
    __syncthreads();
    float pc = spc;
    const float* xr = x + (size_t)b * DD;
    size_t ob = (size_t)b * 1024;
    int d = tid * 2;   // 256 threads x 2 = 512
    float2 v = *(const float2*)(xr + d);
    __half2 h0; h0.x = __float2half_rn(v.x); h0.y = __float2half_rn(v.y);
    __half2 h1; h1.x = __float2half_rn(pc * v.x); h1.y = __float2half_rn(pc * v.y);
    *(__half2*)(cxh + ob + d) = h0;
    *(__half2*)(cxh + ob + 512 + d) = h1;
}

// cgate via collapsed u: logits_e = x.u0[:,e] + pctr*(x.u1[:,e]) + cgb
__global__ void cgate_kernel(const float* __restrict__ x, const float* __restrict__ out,
                             const float* __restrict__ u, const float* __restrict__ cgb,
                             float* __restrict__ cg)
{
    int gw = (blockIdx.x * blockDim.x + threadIdx.x) >> 5;
    int lane = threadIdx.x & 31;
    if (gw >= NB) return;
    const float* xr = x + (size_t)gw * DD;
    float a0[8] = {}, a1[8] = {};
    for (int d = lane; d < DD; d += 32) {
        float xv = xr[d];
        const float* u0 = u + (size_t)d * 8;
        const float* u1 = u + (size_t)(DD + d) * 8;
        float4 w0 = *(const float4*)u0;
        float4 w1 = *(const float4*)(u0 + 4);
        a0[0] += xv * w0.x; a0[1] += xv * w0.y; a0[2] += xv * w0.z; a0[3] += xv * w0.w;
        a0[4] += xv * w1.x; a0[5] += xv * w1.y; a0[6] += xv * w1.z; a0[7] += xv * w1.w;
        float4 v0 = *(const float4*)u1;
        float4 v1 = *(const float4*)(u1 + 4);
        a1[0] += xv * v0.x; a1[1] += xv * v0.y; a1[2] += xv * v0.z; a1[3] += xv * v0.w;
        a1[4] += xv * v1.x; a1[5] += xv * v1.y; a1[6] += xv * v1.z; a1[7] += xv * v1.w;
    }
    #pragma unroll
    for (int e = 0; e < 8; e++) {
        #pragma unroll
        for (int o = 16; o; o >>= 1) {
            a0[e] += __shfl_xor_sync(0xffffffffu, a0[e], o);
            a1[e] += __shfl_xor_sync(0xffffffffu, a1[e], o);
        }
    }
    float pc = out[gw];
    float m = -1e30f;
    float acc[8];
    #pragma unroll
    for (int e = 0; e < 8; e++) {
        acc[e] = a0[e] + pc * a1[e] + cgb[e];
        m = fmaxf(m, acc[e]);
    }
    float s = 0.f;
    #pragma unroll
    for (int e = 0; e < 8; e++) { acc[e] = expf(acc[e] - m); s += acc[e]; }
    float inv = 1.f / s;
    if (lane < 8) cg[(size_t)gw * 8 + lane] = acc[lane] * inv;
}

__global__ void pconv_kernel(const float* __restrict__ outr, const float* __restrict__ cpW,
                             const float* __restrict__ cpb, float* __restrict__ out)
{
    int gw = (blockIdx.x * blockDim.x + threadIdx.x) >> 5;
    int lane = threadIdx.x & 31;
    if (gw >= NB) return;
    const float* ch2 = outr + O8 + (size_t)gw * TT2;
    float s = 0.f;
    for (int m = lane; m < TT2; m += 32) s += ch2[m] * cpW[m];
    #pragma unroll
    for (int o = 16; o; o >>= 1) s += __shfl_xor_sync(0xffffffffu, s, o);
    if (lane == 0) out[O2 + gw] = 1.f / (1.f + expf(-(s + cpb[0])));
}

// ============================================================
extern "C" void kernel_launch(void* const* d_in, const int* in_sizes, int n_in,
                              void* d_out, int out_size)
{
    const float* x    = (const float*)d_in[0];
    const float* eW1  = (const float*)d_in[1];
    const float* eb1  = (const float*)d_in[2];
    const float* eW2  = (const float*)d_in[3];
    const float* eb2  = (const float*)d_in[4];
    const float* gW   = (const float*)d_in[5];
    const float* gb   = (const float*)d_in[6];
    const float* tW1  = (const float*)d_in[7];
    const float* tb1  = (const float*)d_in[8];
    const float* tW2  = (const float*)d_in[9];
    const float* tb2  = (const float*)d_in[10];
    const float* pW   = (const float*)d_in[11];
    const float* pb   = (const float*)d_in[12];
    const float* embW = (const float*)d_in[13];
    const float* embB = (const float*)d_in[14];
    const float* ceW1 = (const float*)d_in[15];
    const float* ceb1 = (const float*)d_in[16];
    const float* ceW2 = (const float*)d_in[17];
    const float* ceb2 = (const float*)d_in[18];
    const float* cgW  = (const float*)d_in[19];
    const float* cgb  = (const float*)d_in[20];
    const float* ctW1 = (const float*)d_in[21];
    const float* ctb1 = (const float*)d_in[22];
    const float* ctW2 = (const float*)d_in[23];
    const float* ctb2 = (const float*)d_in[24];
    const float* cpW  = (const float*)d_in[25];
    const float* cpb  = (const float*)d_in[26];
    float* out = (float*)d_out;

    __half *xh, *cxh, *Hh, *FEAh, *W1h, *W2h, *CUh, *CW2h, *tW1h, *tW2h, *cW1h, *cW2h;
    __half *tfh, *th1h, *cth, *ch1h;
    float *pG, *pCG, *pUG;
    cudaGetSymbolAddress((void**)&xh, g_xh);
    cudaGetSymbolAddress((void**)&cxh, g_cxh);
    cudaGetSymbolAddress((void**)&Hh, g_Hh);
    cudaGetSymbolAddress((void**)&FEAh, g_FEAh);
    cudaGetSymbolAddress((void**)&W1h, g_W1h); cudaGetSymbolAddress((void**)&W2h, g_W2h);
    cudaGetSymbolAddress((void**)&CUh, g_CUh); cudaGetSymbolAddress((void**)&CW2h, g_CW2h);
    cudaGetSymbolAddress((void**)&tW1h, g_tW1h); cudaGetSymbolAddress((void**)&tW2h, g_tW2h);
    cudaGetSymbolAddress((void**)&cW1h, g_cW1h); cudaGetSymbolAddress((void**)&cW2h, g_cW2h);
    cudaGetSymbolAddress((void**)&tfh, g_tfh);
    cudaGetSymbolAddress((void**)&th1h, g_th1h);
    cudaGetSymbolAddress((void**)&cth, g_cth);
    cudaGetSymbolAddress((void**)&ch1h, g_ch1h);
    cudaGetSymbolAddress((void**)&pG, g_GATES);
    cudaGetSymbolAddress((void**)&pCG, g_CGATE);
    cudaGetSymbolAddress((void**)&pUG, g_UG);

    const int SM1 = 3 * 2 * 16384;   // 98304, 2 CTAs/SM
    cudaFuncSetAttribute(hmma_t, cudaFuncAttributeMaxDynamicSharedMemorySize, SM1);
    dim3 blk(256);
    dim3 tb(32, 8);

    // ---- side stream + fork/join events (created once; host-side only) ----
    static cudaStream_t s2 = nullptr;
    static cudaEvent_t evFork = nullptr, evPrep = nullptr, evPred = nullptr, evCg = nullptr;
    if (s2 == nullptr) {
        cudaStreamCreateWithFlags(&s2, cudaStreamNonBlocking);
        cudaEventCreateWithFlags(&evFork, cudaEventDisableTiming);
        cudaEventCreateWithFlags(&evPrep, cudaEventDisableTiming);
        cudaEventCreateWithFlags(&evPred, cudaEventDisableTiming);
        cudaEventCreateWithFlags(&evCg,   cudaEventDisableTiming);
    }

    // fork s2 from the main (legacy) stream
    cudaEventRecord(evFork, 0);
    cudaStreamWaitEvent(s2, evFork, 0);

    // ---- side stream: all prep not needed for E1, plus gates ----
    transpose_h<<<dim3(NH2 / 32, NH1 / 32, NE), tb, 0, s2>>>(eW2, W2h, NH1, NH2);
    prep_cu<<<dim3(NH1 / 32, DD / 32, NE), tb, 0, s2>>>(ceW1, embW, embB, CUh);
    transpose_h<<<dim3(NH2 / 32, NH1 / 32, NE), tb, 0, s2>>>(ceW2, CW2h, NH1, NH2);
    transpose_h<<<dim3(TT1 / 32, NH2 / 32, 2), tb, 0, s2>>>(tW1, tW1h, NH2, TT1);
    transpose_h<<<dim3(TT2 / 32, TT1 / 32, 2), tb, 0, s2>>>(tW2, tW2h, TT1, TT2);
    transpose_h<<<dim3(TT1 / 32, NH2 / 32, 1), tb, 0, s2>>>(ctW1, cW1h, NH2, TT1);
    transpose_h<<<dim3(TT2 / 32, TT1 / 32, 1), tb, 0, s2>>>(ctW2, cW2h, TT1, TT2);
    prep_ug<<<(DD * 8 + 255) / 256, 256, 0, s2>>>(cgW, embW, embB, pUG);
    gates_kernel<<<NB * 2 / 8, 256, 0, s2>>>(x, gW, gb, pG);
    cudaEventRecord(evPrep, s2);

    // ---- main stream: critical path ----
    transpose_h<<<dim3(NH1 / 32, DD / 32, NE), tb>>>(eW1, W1h, DD, NH1);
    convert_h<<<NB * DD / 4 / 256, 256>>>(x, xh, (size_t)NB * DD);

    hmma_t<<<dim3(NH1 / 128, NB / 128, NE), blk, SM1>>>(
        xh, W1h, eb1, nullptr, Hh,
        NH1, DD, 15, DD, 0, (size_t)NH1 * DD, NH1, (size_t)NB * NH1, 2);

    // join: E2 and everything after need W2h/gates/CUh/... from s2
    cudaStreamWaitEvent(0, evPrep, 0);

    hmma_t<<<dim3(NH2 / 128, NB / 128, NE), blk, SM1>>>(
        Hh, W2h, eb2, nullptr, FEAh,
        NH2, NH1, 31, NH1, (size_t)NB * NH1, (size_t)NH2 * NH1, NH2, (size_t)NB * NH2, 2);

    combine12<<<NB, 256>>>(FEAh, pG, out + O3, out + O4, tfh);

    // towers (one-pass, 2 CTAs/SM)
    hmma_t<<<dim3(TT1 / 128, NB / 128, 2), blk, SM1>>>(
        tfh, tW1h, tb1, nullptr, th1h,
        TT1, NH2, 15, NH2, (size_t)NB * NH2, (size_t)TT1 * NH2, TT1, (size_t)NB * TT1, 2);
    hmma_t<<<dim3(1, NB / 128, 2), blk, SM1>>>(
        th1h, tW2h, tb2, out + O6, nullptr,
        TT2, TT1, 7, TT1, (size_t)NB * TT1, (size_t)TT2 * TT1, TT2, (size_t)NB * TT2, 0);

    // fused preds + cx (writes pctr/pcvr and cxh in one pass)
    preds_cx_kernel<<<NB, 256>>>(x, out, pW, pb, out, cxh);

    // fork: cgate on s2 (needs pctr + UG), concurrent with CE1/CE2
    cudaEventRecord(evPred, 0);
    cudaStreamWaitEvent(s2, evPred, 0);
    cgate_kernel<<<NB / 8, 256, 0, s2>>>(x, out, pUG, cgb, pCG);
    cudaEventRecord(evCg, s2);

    // ---- phase 2 on main stream ----
    hmma_t<<<dim3(NH1 / 128, NB / 128, NE), blk, SM1>>>(
        cxh, CUh, ceb1, nullptr, Hh,
        NH1, 1024, 31, 1024, 0, (size_t)NH1 * 1024, NH1, (size_t)NB * NH1, 2);
    hmma_t<<<dim3(NH2 / 128, NB / 128, NE), blk, SM1>>>(
        Hh, CW2h, ceb2, nullptr, FEAh,
        NH2, NH1, 31, NH1, (size_t)NB * NH1, (size_t)NH2 * NH1, NH2, (size_t)NB * NH2, 2);

    // join cgate before combine1c
    cudaStreamWaitEvent(0, evCg, 0);
    combine1c<<<NB, 256>>>(FEAh, pCG, out + O5, cth);

    hmma_t<<<dim3(TT1 / 128, NB / 128, 1), blk, SM1>>>(
        cth, cW1h, ctb1, nullptr, ch1h,
        TT1, NH2, 15, NH2, 0, 0, 0, (size_t)NB * TT1, 2);
    hmma_t<<<dim3(1, NB / 128, 1), blk, SM1>>>(
        ch1h, cW2h, ctb2, out + O8, nullptr,
        TT2, TT1, 7, TT1, 0, 0, 0, 0, 0);
    pconv_kernel<<<NB / 8, 256>>>(out, cpW, cpb, out);
}

// round 16
// speedup vs baseline: 1.0032x; 1.0032x over previous
#include <cuda_runtime.h>
#include <cuda_fp16.h>
#include <math.h>

typedef unsigned long long ull;
typedef unsigned int u32;

#define NB   16384
#define DD   512
#define NE   8
#define NH1  1024
#define NH2  512
#define TT1  256
#define TT2  128
#define PEN  5
#define KAIT 2560   // D*PE

// ---- output layout ----
#define O0 ((size_t)0)
#define O1 ((size_t)NB)
#define O2 ((size_t)2*NB)
#define O3 ((size_t)3*NB)
#define O4 (O3 + (size_t)NB*512)
#define O5 (O4 + (size_t)NB*512)
#define O6 (O5 + (size_t)NB*512)
#define O7 (O6 + (size_t)NB*128)
#define O8 (O7 + (size_t)NB*128)

// ---- scratch ----
__device__ __half g_xh [(size_t)NB*DD];
__device__ __half g_cxh[(size_t)NB*1024];   // [x | pctr*x] hi only
__device__ __half g_Hh [(size_t)NE*NB*NH1];
__device__ __half g_FEAh[(size_t)NE*NB*NH2];
__device__ __half g_W1h[(size_t)NE*NH1*DD];
__device__ __half g_W2h[(size_t)NE*NH2*NH1];
__device__ __half g_CUh[(size_t)NE*NH1*1024];  // [U0;U1] per expert, [N][1024]
__device__ __half g_CW2h[(size_t)NE*NH2*NH1];
__device__ __half g_tW1h[(size_t)2*TT1*NH2];
__device__ __half g_tW2h[(size_t)2*TT2*TT1];
__device__ __half g_cW1h[(size_t)TT1*NH2];
__device__ __half g_cW2h[(size_t)TT2*TT1];
__device__ __half g_tfh[(size_t)2*NB*NH2];
__device__ __half g_th1h[(size_t)2*NB*TT1];
__device__ __half g_cth[(size_t)NB*NH2];
__device__ __half g_ch1h[(size_t)NB*TT1];
__device__ float g_GATES[(size_t)NB*2*8];
__device__ float g_CGATE[(size_t)NB*8];
__device__ float g_UG  [(size_t)2*DD*8];    // cgate u0/u1

// ================= helpers =================
__device__ __forceinline__ u32 smem_u32(const void* p) {
    u32 a;
    asm("{ .reg .u64 t; cvta.to.shared.u64 t, %1; cvt.u32.u64 %0, t; }" : "=r"(a) : "l"(p));
    return a;
}
__device__ __forceinline__ void cpa16(u32 dst, const void* src) {
    asm volatile("cp.async.cg.shared.global [%0], [%1], 16;" :: "r"(dst), "l"(src) : "memory");
}
#define CPA_COMMIT() asm volatile("cp.async.commit_group;" ::: "memory")
#define CPA_WAIT1()  asm volatile("cp.async.wait_group 1;" ::: "memory")

__device__ __forceinline__ void mma16816(float* c, const u32* a, const u32* b) {
    asm volatile(
        "mma.sync.aligned.m16n8k16.row.col.f32.f16.f16.f32 "
        "{%0,%1,%2,%3}, {%4,%5,%6,%7}, {%8,%9}, {%0,%1,%2,%3};"
        : "+f"(c[0]), "+f"(c[1]), "+f"(c[2]), "+f"(c[3])
        : "r"(a[0]), "r"(a[1]), "r"(a[2]), "r"(a[3]), "r"(b[0]), "r"(b[1]));
}

// swizzled smem offset (64B rows, 4x16B chunks)
__device__ __forceinline__ u32 swz(int row, int ch) {
    return (u32)(row * 64 + ((ch ^ ((row >> 1) & 3)) << 4));
}

__device__ __forceinline__ void ldA(u32 tb, int row0, int s, u32* a) {
    int lane = threadIdx.x & 31;
    int g = lane >> 3, li = lane & 7;
    int row = row0 + ((g & 1) << 3) + li;
    int ch = 2 * s + (g >> 1);
    u32 addr = tb + swz(row, ch);
    asm volatile("ldmatrix.sync.aligned.m8n8.x4.shared.b16 {%0,%1,%2,%3}, [%4];"
        : "=r"(a[0]), "=r"(a[1]), "=r"(a[2]), "=r"(a[3]) : "r"(addr));
}
__device__ __forceinline__ void ldB(u32 tb, int n0, int s, u32* r) {
    int lane = threadIdx.x & 31;
    int g = lane >> 3, li = lane & 7;
    int row = n0 + ((g >> 1) << 3) + li;
    int ch = 2 * s + (g & 1);
    u32 addr = tb + swz(row, ch);
    asm volatile("ldmatrix.sync.aligned.m8n8.x4.shared.b16 {%0,%1,%2,%3}, [%4];"
        : "=r"(r[0]), "=r"(r[1]), "=r"(r[2]), "=r"(r[3]) : "r"(addr));
}

// ============================================================
// HMMA GEMM, one-pass, k=64 chunks, 3-stage cp.async pipeline.
//   C[z] = relu(A[z] @ B[z]^T + bias[z])
// A [M, aK] fp16; B [N, K] fp16 (pre-transposed).
// A k-col for 32-chunk c32 = (c32 & acolmask)*32.  K % 64 == 0, K >= 128.
// 96KB smem -> 2 CTAs/SM.
// mode: 0 = fp32 C, 2 = fp16 C.
// ============================================================
__global__ void __launch_bounds__(256, 2) hmma_t(
    const __half* __restrict__ Ah,
    const __half* __restrict__ Bh, const float* __restrict__ bias,
    float* __restrict__ Cf, __half* __restrict__ Ch,
    int N, int K, int acolmask, int aK,
    size_t sA, size_t sB, size_t sBias, size_t sC, int mode)
{
    extern __shared__ char dsm[];
    const int SUB   = 16384;
    const int STAGE = 2 * SUB;
    const int NSLOT = 4;
    const int tid = threadIdx.x;
    const int wid = tid >> 5;
    const int lane = tid & 31;
    const int z = blockIdx.z;
    const int bm = blockIdx.y << 7;
    const int bn = blockIdx.x << 7;

    Ah += (size_t)z * sA;
    Bh += (size_t)z * sB;  bias += (size_t)z * sBias;

    const u32 sbase = smem_u32(dsm);

    u32 soff[NSLOT];
    const __half* gsrc[NSLOT];
    u32 amask[NSLOT];
    #pragma unroll
    for (int j = 0; j < NSLOT; j++) {
        int sid = tid + (j << 8);
        int buf = sid >> 9;
        int rem = sid & 511;
        int r = rem >> 2;
        int ch = rem & 3;
        soff[j] = (u32)(buf * 8192) + swz(r, ch);
        bool isA = (buf == 0);
        const __half* base = isA ? Ah : Bh;
        int grow = (isA ? bm : bn) + r;
        gsrc[j] = base + (size_t)grow * (isA ? aK : K) + ch * 8;
        amask[j] = isA ? (u32)acolmask : 0xFFFFFFFFu;
    }

    const int nch = K >> 6;   // 64-k chunks

    // prologue: fill stages 0,1
    #pragma unroll
    for (int p = 0; p < 2; p++) {
        u32 sb = sbase + (u32)p * STAGE;
        #pragma unroll
        for (int sc = 0; sc < 2; sc++)
            #pragma unroll
            for (int j = 0; j < NSLOT; j++)
                cpa16(sb + (u32)sc * SUB + soff[j],
                      gsrc[j] + (((u32)(2 * p + sc) & amask[j]) << 5));
        CPA_COMMIT();
    }

    const int wm = (wid & 3) << 5;
    const int wn = (wid >> 2) << 6;
    const u32 Boff = 8192u;

    float acc[2][8][4];
    #pragma unroll
    for (int i = 0; i < 2; i++)
        #pragma unroll
        for (int j = 0; j < 8; j++)
            #pragma unroll
            for (int q = 0; q < 4; q++) acc[i][j][q] = 0.f;

    int stg = 0;   // i % 3
    for (int i = 0; i < nch; i++) {
        CPA_WAIT1();
        __syncthreads();
        int pf = i + 2;
        if (pf < nch) {
            int pstg = stg + 2; if (pstg >= 3) pstg -= 3;
            u32 sb = sbase + (u32)pstg * STAGE;
            #pragma unroll
            for (int sc = 0; sc < 2; sc++)
                #pragma unroll
                for (int j = 0; j < NSLOT; j++)
                    cpa16(sb + (u32)sc * SUB + soff[j],
                          gsrc[j] + (((u32)(2 * pf + sc) & amask[j]) << 5));
        }
        CPA_COMMIT();

        #pragma unroll
        for (int sc = 0; sc < 2; sc++) {
            u32 stb = sbase + (u32)stg * STAGE + (u32)sc * SUB;
            #pragma unroll
            for (int s = 0; s < 2; s++) {
                u32 ah[2][4], b[8][2];
                ldA(stb, wm,      s, ah[0]);
                ldA(stb, wm + 16, s, ah[1]);
                #pragma unroll
                for (int j4 = 0; j4 < 4; j4++) {
                    u32 r[4];
                    ldB(stb + Boff, wn + j4 * 16, s, r);
                    b[2 * j4][0] = r[0]; b[2 * j4][1] = r[1];
                    b[2 * j4 + 1][0] = r[2]; b[2 * j4 + 1][1] = r[3];
                }
                #pragma unroll
                for (int i2 = 0; i2 < 2; i2++)
                    #pragma unroll
                    for (int j8 = 0; j8 < 8; j8++) mma16816(acc[i2][j8], ah[i2], b[j8]);
            }
        }
        if (++stg == 3) stg = 0;
    }

    // epilogue
    const int r0b = bm + wm + (lane >> 2);
    const int c0b = bn + wn + ((lane & 3) << 1);
    #pragma unroll
    for (int i2 = 0; i2 < 2; i2++) {
        #pragma unroll
        for (int j8 = 0; j8 < 8; j8++) {
            int col = c0b + j8 * 8;
            float b0 = bias[col], b1 = bias[col + 1];
            #pragma unroll
            for (int h = 0; h < 2; h++) {
                int row = r0b + i2 * 16 + h * 8;
                float v0 = fmaxf(acc[i2][j8][2 * h]     + b0, 0.f);
                float v1 = fmaxf(acc[i2][j8][2 * h + 1] + b1, 0.f);
                if (mode == 0) {
                    *(float2*)(Cf + (size_t)z * sC + (size_t)row * N + col) = make_float2(v0, v1);
                } else {
                    __half2 hp;
                    hp.x = __float2half_rn(v0);
                    hp.y = __float2half_rn(v1);
                    *(__half2*)(Ch + (size_t)z * sC + (size_t)row * N + col) = hp;
                }
            }
        }
    }
}

// ============================================================
// weight transpose: W[z][K][N] f32 -> T[z][N][K] fp16
// ============================================================
__global__ void transpose_h(const float* __restrict__ W, __half* __restrict__ Th,
                            int Kd, int Nd)
{
    __shared__ float t[32][33];
    int z = blockIdx.z;
    const float* Wz = W + (size_t)z * Kd * Nd;
    int n0 = blockIdx.x << 5, k0 = blockIdx.y << 5;
    for (int r = threadIdx.y; r < 32; r += 8)
        t[r][threadIdx.x] = Wz[(size_t)(k0 + r) * Nd + n0 + threadIdx.x];
    __syncthreads();
    size_t ob = (size_t)z * Nd * Kd;
    for (int r = threadIdx.y; r < 32; r += 8)
        Th[ob + (size_t)(n0 + r) * Kd + k0 + threadIdx.x] = __float2half_rn(t[threadIdx.x][r]);
}

// CE1 collapse: ceW1[z][d*5+p][n] f32 -> CU[z][n][d] = sum_p embB_p*W,
//                                        CU[z][n][512+d] = sum_p embW_p*W
__global__ void prep_cu(const float* __restrict__ W, const float* __restrict__ embW,
                        const float* __restrict__ embB, __half* __restrict__ CU)
{
    __shared__ float t0[32][33], t1[32][33];
    int z = blockIdx.z;
    int n0 = blockIdx.x << 5, d0 = blockIdx.y << 5;
    const float* Wz = W + (size_t)z * KAIT * NH1;
    float ew[PEN], eb[PEN];
    #pragma unroll
    for (int p = 0; p < PEN; p++) { ew[p] = embW[p]; eb[p] = embB[p]; }
    for (int r = threadIdx.y; r < 32; r += 8) {
        float s0 = 0.f, s1 = 0.f;
        #pragma unroll
        for (int p = 0; p < PEN; p++) {
            float w = Wz[(size_t)((d0 + r) * PEN + p) * NH1 + n0 + threadIdx.x];
            s0 += eb[p] * w;
            s1 += ew[p] * w;
        }
        t0[r][threadIdx.x] = s0;
        t1[r][threadIdx.x] = s1;
    }
    __syncthreads();
    size_t ob = (size_t)z * NH1 * 1024;
    for (int r = threadIdx.y; r < 32; r += 8) {
        CU[ob + (size_t)(n0 + r) * 1024 + d0 + threadIdx.x] =
            __float2half_rn(t0[threadIdx.x][r]);
        CU[ob + (size_t)(n0 + r) * 1024 + 512 + d0 + threadIdx.x] =
            __float2half_rn(t1[threadIdx.x][r]);
    }
}

// cgate collapse: u0[d][e] = sum_p embB_p*cgW[d*5+p][e]; u1 likewise with embW
__global__ void prep_ug(const float* __restrict__ cgW, const float* __restrict__ embW,
                        const float* __restrict__ embB, float* __restrict__ u)
{
    int i = blockIdx.x * blockDim.x + threadIdx.x;
    if (i >= DD * 8) return;
    int d = i >> 3, e = i & 7;
    float s0 = 0.f, s1 = 0.f;
    #pragma unroll
    for (int p = 0; p < PEN; p++) {
        float w = cgW[(size_t)(d * PEN + p) * 8 + e];
        s0 += embB[p] * w;
        s1 += embW[p] * w;
    }
    u[i] = s0;
    u[DD * 8 + i] = s1;
}

// elementwise fp32 -> fp16 (hi only)
__global__ void convert_h(const float* __restrict__ src, __half* __restrict__ hi, size_t n)
{
    size_t i = ((size_t)blockIdx.x * blockDim.x + threadIdx.x) * 4;
    if (i >= n) return;
    float4 v = *(const float4*)(src + i);
    __half2 a, b;
    a.x = __float2half_rn(v.x); a.y = __float2half_rn(v.y);
    b.x = __float2half_rn(v.z); b.y = __float2half_rn(v.w);
    *(__half2*)(hi + i) = a; *(__half2*)(hi + i + 2) = b;
}

// cx[b] = [x[b] | pctr[b]*x[b]] fp16 hi only (CE1 A operand), vectorized
__global__ void cx_kernel(const float* __restrict__ x, const float* __restrict__ out,
                          __half* __restrict__ cxh)
{
    int b = blockIdx.x;
    float pc = out[b];
    const float* xr = x + (size_t)b * DD;
    size_t ob = (size_t)b * 1024;
    int d = threadIdx.x * 2;   // 256 threads x 2 = 512
    float2 v = *(const float2*)(xr + d);
    __half2 h0; h0.x = __float2half_rn(v.x); h0.y = __float2half_rn(v.y);
    __half2 h1; h1.x = __float2half_rn(pc * v.x); h1.y = __float2half_rn(pc * v.y);
    *(__half2*)(cxh + ob + d) = h0;
    *(__half2*)(cxh + ob + 512 + d) = h1;
}

// ================= small fp32 kernels =================
__global__ void gates_kernel(const float* __restrict__ x, const float* __restrict__ gW,
                             const float* __restrict__ gb, float* __restrict__ gates)
{
    int gw = (blockIdx.x * blockDim.x + threadIdx.x) >> 5;
    int lane = threadIdx.x & 31;
    if (gw >= NB * 2) return;
    int b = gw >> 1, t = gw & 1;
    const float* xr = x + (size_t)b * DD;
    float acc[8] = {};
    for (int d = lane; d < DD; d += 32) {
        float xv = xr[d];
        const float* g = gW + ((size_t)t * DD + d) * NE;
        float4 w0 = *(const float4*)g;
        float4 w1 = *(const float4*)(g + 4);
        acc[0] += xv * w0.x; acc[1] += xv * w0.y; acc[2] += xv * w0.z; acc[3] += xv * w0.w;
        acc[4] += xv * w1.x; acc[5] += xv * w1.y; acc[6] += xv * w1.z; acc[7] += xv * w1.w;
    }
    #pragma unroll
    for (int e = 0; e < 8; e++)
        #pragma unroll
        for (int o = 16; o; o >>= 1) acc[e] += __shfl_xor_sync(0xffffffffu, acc[e], o);
    float m = -1e30f;
    #pragma unroll
    for (int e = 0; e < 8; e++) { acc[e] += gb[t * 8 + e]; m = fmaxf(m, acc[e]); }
    float s = 0.f;
    #pragma unroll
    for (int e = 0; e < 8; e++) { acc[e] = expf(acc[e] - m); s += acc[e]; }
    float inv = 1.f / s;
    if (lane < 8) gates[((size_t)b * 2 + t) * 8 + lane] = acc[lane] * inv;
}

// fused combine for both tasks + fp16 task_fea (tower input); FEA is fp16
__global__ void combine12(const __half* __restrict__ fea, const float* __restrict__ gates,
                          float* __restrict__ o3, float* __restrict__ o4,
                          __half* __restrict__ tfh)
{
    int b = blockIdx.x;
    __shared__ float g[16];
    if (threadIdx.x < 16) g[threadIdx.x] = gates[(size_t)b * 16 + threadIdx.x];
    __syncthreads();
    const __half* f = fea + (size_t)b * NH2;
    for (int h = threadIdx.x; h < NH2; h += blockDim.x) {
        float s0 = 0.f, s1 = 0.f;
        #pragma unroll
        for (int e = 0; e < 8; e++) {
            float v = __half2float(f[(size_t)e * NB * NH2 + h]);
            s0 += g[e] * v;
            s1 += g[8 + e] * v;
        }
        o3[(size_t)b * NH2 + h] = s0;
        o4[(size_t)b * NH2 + h] = s1;
        tfh[(size_t)b * NH2 + h] = __float2half_rn(s0);
        tfh[(size_t)(NB + b) * NH2 + h] = __float2half_rn(s1);
    }
}

// phase-2 combine: ctask -> O5 + fp16 for cascade tower; FEA is fp16
__global__ void combine1c(const __half* __restrict__ fea, const float* __restrict__ cg,
                          float* __restrict__ o5, __half* __restrict__ cth)
{
    int b = blockIdx.x;
    __shared__ float g[8];
    if (threadIdx.x < 8) g[threadIdx.x] = cg[(size_t)b * 8 + threadIdx.x];
    __syncthreads();
    const __half* f = fea + (size_t)b * NH2;
    for (int h = threadIdx.x; h < NH2; h += blockDim.x) {
        float s = 0.f;
        #pragma unroll
        for (int e = 0; e < 8; e++) s += g[e] * __half2float(f[(size_t)e * NB * NH2 + h]);
        o5[(size_t)b * NH2 + h] = s;
        cth[(size_t)b * NH2 + h] = __float2half_rn(s);
    }
}

__global__ void preds_kernel(const float* __restrict__ outr, const float* __restrict__ pW,
                             const float* __restrict__ pb, float* __restrict__ out)
{
    int gw = (blockIdx.x * blockDim.x + threadIdx.x) >> 5;
    int lane = threadIdx.x & 31;
    if (gw >= NB * 2) return;
    int b = gw >> 1, t = gw & 1;
    const float* th2 = outr + O6 + (size_t)t * NB * TT2 + (size_t)b * TT2;
    const float* w = pW + t * TT2;
    float s = 0.f;
    for (int m = lane; m < TT2; m += 32) s += th2[m] * w[m];
    #pragma unroll
    for (int o = 16; o; o >>= 1) s += __shfl_xor_sync(0xffffffffu, s, o);
    if (lane == 0) {
        s += pb[t];
        out[(size_t)t * NB + b] = 1.f / (1.f + expf(-s));
    }
}

// cgate via collapsed u: logits_e = x.u0[:,e] + pctr*(x.u1[:,e]) + cgb
__global__ void cgate_kernel(const float* __restrict__ x, const float* __restrict__ out,
                             const float* __restrict__ u, const float* __restrict__ cgb,
                             float* __restrict__ cg)
{
    int gw = (blockIdx.x * blockDim.x + threadIdx.x) >> 5;
    int lane = threadIdx.x & 31;
    if (gw >= NB) return;
    const float* xr = x + (size_t)gw * DD;
    float a0[8] = {}, a1[8] = {};
    for (int d = lane; d < DD; d += 32) {
        float xv = xr[d];
        const float* u0 = u + (size_t)d * 8;
        const float* u1 = u + (size_t)(DD + d) * 8;
        float4 w0 = *(const float4*)u0;
        float4 w1 = *(const float4*)(u0 + 4);
        a0[0] += xv * w0.x; a0[1] += xv * w0.y; a0[2] += xv * w0.z; a0[3] += xv * w0.w;
        a0[4] += xv * w1.x; a0[5] += xv * w1.y; a0[6] += xv * w1.z; a0[7] += xv * w1.w;
        float4 v0 = *(const float4*)u1;
        float4 v1 = *(const float4*)(u1 + 4);
        a1[0] += xv * v0.x; a1[1] += xv * v0.y; a1[2] += xv * v0.z; a1[3] += xv * v0.w;
        a1[4] += xv * v1.x; a1[5] += xv * v1.y; a1[6] += xv * v1.z; a1[7] += xv * v1.w;
    }
    #pragma unroll
    for (int e = 0; e < 8; e++) {
        #pragma unroll
        for (int o = 16; o; o >>= 1) {
            a0[e] += __shfl_xor_sync(0xffffffffu, a0[e], o);
            a1[e] += __shfl_xor_sync(0xffffffffu, a1[e], o);
        }
    }
    float pc = out[gw];
    float m = -1e30f;
    float acc[8];
    #pragma unroll
    for (int e = 0; e < 8; e++) {
        acc[e] = a0[e] + pc * a1[e] + cgb[e];
        m = fmaxf(m, acc[e]);
    }
    float s = 0.f;
    #pragma unroll
    for (int e = 0; e < 8; e++) { acc[e] = expf(acc[e] - m); s += acc[e]; }
    float inv = 1.f / s;
    if (lane < 8) cg[(size_t)gw * 8 + lane] = acc[lane] * inv;
}

__global__ void pconv_kernel(const float* __restrict__ outr, const float* __restrict__ cpW,
                             const float* __restrict__ cpb, float* __restrict__ out)
{
    int gw = (blockIdx.x * blockDim.x + threadIdx.x) >> 5;
    int lane = threadIdx.x & 31;
    if (gw >= NB) return;
    const float* ch2 = outr + O8 + (size_t)gw * TT2;
    float s = 0.f;
    for (int m = lane; m < TT2; m += 32) s += ch2[m] * cpW[m];
    #pragma unroll
    for (int o = 16; o; o >>= 1) s += __shfl_xor_sync(0xffffffffu, s, o);
    if (lane == 0) out[O2 + gw] = 1.f / (1.f + expf(-(s + cpb[0])));
}

// ============================================================
extern "C" void kernel_launch(void* const* d_in, const int* in_sizes, int n_in,
                              void* d_out, int out_size)
{
    const float* x    = (const float*)d_in[0];
    const float* eW1  = (const float*)d_in[1];
    const float* eb1  = (const float*)d_in[2];
    const float* eW2  = (const float*)d_in[3];
    const float* eb2  = (const float*)d_in[4];
    const float* gW   = (const float*)d_in[5];
    const float* gb   = (const float*)d_in[6];
    const float* tW1  = (const float*)d_in[7];
    const float* tb1  = (const float*)d_in[8];
    const float* tW2  = (const float*)d_in[9];
    const float* tb2  = (const float*)d_in[10];
    const float* pW   = (const float*)d_in[11];
    const float* pb   = (const float*)d_in[12];
    const float* embW = (const float*)d_in[13];
    const float* embB = (const float*)d_in[14];
    const float* ceW1 = (const float*)d_in[15];
    const float* ceb1 = (const float*)d_in[16];
    const float* ceW2 = (const float*)d_in[17];
    const float* ceb2 = (const float*)d_in[18];
    const float* cgW  = (const float*)d_in[19];
    const float* cgb  = (const float*)d_in[20];
    const float* ctW1 = (const float*)d_in[21];
    const float* ctb1 = (const float*)d_in[22];
    const float* ctW2 = (const float*)d_in[23];
    const float* ctb2 = (const float*)d_in[24];
    const float* cpW  = (const float*)d_in[25];
    const float* cpb  = (const float*)d_in[26];
    float* out = (float*)d_out;

    __half *xh, *cxh, *Hh, *FEAh, *W1h, *W2h, *CUh, *CW2h, *tW1h, *tW2h, *cW1h, *cW2h;
    __half *tfh, *th1h, *cth, *ch1h;
    float *pG, *pCG, *pUG;
    cudaGetSymbolAddress((void**)&xh, g_xh);
    cudaGetSymbolAddress((void**)&cxh, g_cxh);
    cudaGetSymbolAddress((void**)&Hh, g_Hh);
    cudaGetSymbolAddress((void**)&FEAh, g_FEAh);
    cudaGetSymbolAddress((void**)&W1h, g_W1h); cudaGetSymbolAddress((void**)&W2h, g_W2h);
    cudaGetSymbolAddress((void**)&CUh, g_CUh); cudaGetSymbolAddress((void**)&CW2h, g_CW2h);
    cudaGetSymbolAddress((void**)&tW1h, g_tW1h); cudaGetSymbolAddress((void**)&tW2h, g_tW2h);
    cudaGetSymbolAddress((void**)&cW1h, g_cW1h); cudaGetSymbolAddress((void**)&cW2h, g_cW2h);
    cudaGetSymbolAddress((void**)&tfh, g_tfh);
    cudaGetSymbolAddress((void**)&th1h, g_th1h);
    cudaGetSymbolAddress((void**)&cth, g_cth);
    cudaGetSymbolAddress((void**)&ch1h, g_ch1h);
    cudaGetSymbolAddress((void**)&pG, g_GATES);
    cudaGetSymbolAddress((void**)&pCG, g_CGATE);
    cudaGetSymbolAddress((void**)&pUG, g_UG);

    const int SM1 = 3 * 2 * 16384;   // 98304, 2 CTAs/SM
    cudaFuncSetAttribute(hmma_t, cudaFuncAttributeMaxDynamicSharedMemorySize, SM1);
    dim3 blk(256);
    dim3 tb(32, 8);

    // ---- side stream + fork/join events (created once; host-side only) ----
    static cudaStream_t s2 = nullptr;
    static cudaEvent_t evFork = nullptr, evPrep = nullptr, evPred = nullptr, evCg = nullptr;
    if (s2 == nullptr) {
        cudaStreamCreateWithFlags(&s2, cudaStreamNonBlocking);
        cudaEventCreateWithFlags(&evFork, cudaEventDisableTiming);
        cudaEventCreateWithFlags(&evPrep, cudaEventDisableTiming);
        cudaEventCreateWithFlags(&evPred, cudaEventDisableTiming);
        cudaEventCreateWithFlags(&evCg,   cudaEventDisableTiming);
    }

    // fork s2 from the main (legacy) stream
    cudaEventRecord(evFork, 0);
    cudaStreamWaitEvent(s2, evFork, 0);

    // ---- side stream: all prep not needed for E1, plus gates ----
    transpose_h<<<dim3(NH2 / 32, NH1 / 32, NE), tb, 0, s2>>>(eW2, W2h, NH1, NH2);
    prep_cu<<<dim3(NH1 / 32, DD / 32, NE), tb, 0, s2>>>(ceW1, embW, embB, CUh);
    transpose_h<<<dim3(NH2 / 32, NH1 / 32, NE), tb, 0, s2>>>(ceW2, CW2h, NH1, NH2);
    transpose_h<<<dim3(TT1 / 32, NH2 / 32, 2), tb, 0, s2>>>(tW1, tW1h, NH2, TT1);
    transpose_h<<<dim3(TT2 / 32, TT1 / 32, 2), tb, 0, s2>>>(tW2, tW2h, TT1, TT2);
    transpose_h<<<dim3(TT1 / 32, NH2 / 32, 1), tb, 0, s2>>>(ctW1, cW1h, NH2, TT1);
    transpose_h<<<dim3(TT2 / 32, TT1 / 32, 1), tb, 0, s2>>>(ctW2, cW2h, TT1, TT2);
    prep_ug<<<(DD * 8 + 255) / 256, 256, 0, s2>>>(cgW, embW, embB, pUG);
    gates_kernel<<<NB * 2 / 8, 256, 0, s2>>>(x, gW, gb, pG);
    cudaEventRecord(evPrep, s2);

    // ---- main stream: critical path ----
    transpose_h<<<dim3(NH1 / 32, DD / 32, NE), tb>>>(eW1, W1h, DD, NH1);
    convert_h<<<NB * DD / 4 / 256, 256>>>(x, xh, (size_t)NB * DD);

    hmma_t<<<dim3(NH1 / 128, NB / 128, NE), blk, SM1>>>(
        xh, W1h, eb1, nullptr, Hh,
        NH1, DD, 15, DD, 0, (size_t)NH1 * DD, NH1, (size_t)NB * NH1, 2);

    // join: E2 and everything after need W2h/gates/CUh/... from s2
    cudaStreamWaitEvent(0, evPrep, 0);

    hmma_t<<<dim3(NH2 / 128, NB / 128, NE), blk, SM1>>>(
        Hh, W2h, eb2, nullptr, FEAh,
        NH2, NH1, 31, NH1, (size_t)NB * NH1, (size_t)NH2 * NH1, NH2, (size_t)NB * NH2, 2);

    combine12<<<NB, 256>>>(FEAh, pG, out + O3, out + O4, tfh);

    // towers (one-pass, 2 CTAs/SM)
    hmma_t<<<dim3(TT1 / 128, NB / 128, 2), blk, SM1>>>(
        tfh, tW1h, tb1, nullptr, th1h,
        TT1, NH2, 15, NH2, (size_t)NB * NH2, (size_t)TT1 * NH2, TT1, (size_t)NB * TT1, 2);
    hmma_t<<<dim3(1, NB / 128, 2), blk, SM1>>>(
        th1h, tW2h, tb2, out + O6, nullptr,
        TT2, TT1, 7, TT1, (size_t)NB * TT1, (size_t)TT2 * TT1, TT2, (size_t)NB * TT2, 0);
    preds_kernel<<<NB * 2 / 8, 256>>>(out, pW, pb, out);

    // fork: cgate on s2 (needs pctr + UG), concurrent with cx/CE1/CE2
    cudaEventRecord(evPred, 0);
    cudaStreamWaitEvent(s2, evPred, 0);
    cgate_kernel<<<NB / 8, 256, 0, s2>>>(x, out, pUG, cgb, pCG);
    cudaEventRecord(evCg, s2);

    // ---- phase 2 on main stream ----
    cx_kernel<<<NB, 256>>>(x, out, cxh);
    hmma_t<<<dim3(NH1 / 128, NB / 128, NE), blk, SM1>>>(
        cxh, CUh, ceb1, nullptr, Hh,
        NH1, 1024, 31, 1024, 0, (size_t)NH1 * 1024, NH1, (size_t)NB * NH1, 2);
    hmma_t<<<dim3(NH2 / 128, NB / 128, NE), blk, SM1>>>(
        Hh, CW2h, ceb2, nullptr, FEAh,
        NH2, NH1, 31, NH1, (size_t)NB * NH1, (size_t)NH2 * NH1, NH2, (size_t)NB * NH2, 2);

    // join cgate before combine1c
    cudaStreamWaitEvent(0, evCg, 0);
    combine1c<<<NB, 256>>>(FEAh, pCG, out + O5, cth);

    hmma_t<<<dim3(TT1 / 128, NB / 128, 1), blk, SM1>>>(
        cth, cW1h, ctb1, nullptr, ch1h,
        TT1, NH2, 15, NH2, 0, 0, 0, (size_t)NB * TT1, 2);
    hmma_t<<<dim3(1, NB / 128, 1), blk, SM1>>>(
        ch1h, cW2h, ctb2, out + O8, nullptr,
        TT2, TT1, 7, TT1, 0, 0, 0, 0, 0);
    pconv_kernel<<<NB / 8, 256>>>(out, cpW, cpb, out);
}

// round 17
// speedup vs baseline: 1.0263x; 1.0230x over previous
#include <cuda_runtime.h>
#include <cuda_fp16.h>
#include <math.h>

typedef unsigned long long ull;
typedef unsigned int u32;

#define NB   16384
#define DD   512
#define NE   8
#define NH1  1024
#define NH2  512
#define TT1  256
#define TT2  128
#define PEN  5
#define KAIT 2560   // D*PE

// ---- output layout ----
#define O0 ((size_t)0)
#define O1 ((size_t)NB)
#define O2 ((size_t)2*NB)
#define O3 ((size_t)3*NB)
#define O4 (O3 + (size_t)NB*512)
#define O5 (O4 + (size_t)NB*512)
#define O6 (O5 + (size_t)NB*512)
#define O7 (O6 + (size_t)NB*128)
#define O8 (O7 + (size_t)NB*128)

// ---- scratch ----
__device__ __half g_xh [(size_t)NB*DD];
__device__ __half g_cxh[(size_t)NB*1024];   // [x | pctr*x] hi only
__device__ __half g_Hh [(size_t)NE*NB*NH1];
__device__ __half g_FEAh[(size_t)NE*NB*NH2];
__device__ __half g_W1h[(size_t)NE*NH1*DD];
__device__ __half g_W2h[(size_t)NE*NH2*NH1];
__device__ __half g_CUh[(size_t)NE*NH1*1024];  // [U0;U1] per expert, [N][1024]
__device__ __half g_CW2h[(size_t)NE*NH2*NH1];
__device__ __half g_tW1h[(size_t)2*TT1*NH2];
__device__ __half g_tW2h[(size_t)2*TT2*TT1];
__device__ __half g_cW1h[(size_t)TT1*NH2];
__device__ __half g_cW2h[(size_t)TT2*TT1];
__device__ __half g_tfh[(size_t)2*NB*NH2];
__device__ __half g_th1h[(size_t)2*NB*TT1];
__device__ __half g_cth[(size_t)NB*NH2];
__device__ __half g_ch1h[(size_t)NB*TT1];
__device__ float g_GATES[(size_t)NB*2*8];
__device__ float g_CGATE[(size_t)NB*8];
__device__ float g_UG  [(size_t)2*DD*8];    // cgate u0/u1

// ================= helpers =================
__device__ __forceinline__ u32 smem_u32(const void* p) {
    u32 a;
    asm("{ .reg .u64 t; cvta.to.shared.u64 t, %1; cvt.u32.u64 %0, t; }" : "=r"(a) : "l"(p));
    return a;
}
__device__ __forceinline__ void cpa16(u32 dst, const void* src) {
    asm volatile("cp.async.cg.shared.global [%0], [%1], 16;" :: "r"(dst), "l"(src) : "memory");
}
#define CPA_COMMIT() asm volatile("cp.async.commit_group;" ::: "memory")
#define CPA_WAIT1()  asm volatile("cp.async.wait_group 1;" ::: "memory")

__device__ __forceinline__ void mma16816(float* c, const u32* a, const u32* b) {
    asm volatile(
        "mma.sync.aligned.m16n8k16.row.col.f32.f16.f16.f32 "
        "{%0,%1,%2,%3}, {%4,%5,%6,%7}, {%8,%9}, {%0,%1,%2,%3};"
        : "+f"(c[0]), "+f"(c[1]), "+f"(c[2]), "+f"(c[3])
        : "r"(a[0]), "r"(a[1]), "r"(a[2]), "r"(a[3]), "r"(b[0]), "r"(b[1]));
}

// swizzled smem offset (64B rows, 4x16B chunks)
__device__ __forceinline__ u32 swz(int row, int ch) {
    return (u32)(row * 64 + ((ch ^ ((row >> 1) & 3)) << 4));
}

__device__ __forceinline__ void ldA(u32 tb, int row0, int s, u32* a) {
    int lane = threadIdx.x & 31;
    int g = lane >> 3, li = lane & 7;
    int row = row0 + ((g & 1) << 3) + li;
    int ch = 2 * s + (g >> 1);
    u32 addr = tb + swz(row, ch);
    asm volatile("ldmatrix.sync.aligned.m8n8.x4.shared.b16 {%0,%1,%2,%3}, [%4];"
        : "=r"(a[0]), "=r"(a[1]), "=r"(a[2]), "=r"(a[3]) : "r"(addr));
}
__device__ __forceinline__ void ldB(u32 tb, int n0, int s, u32* r) {
    int lane = threadIdx.x & 31;
    int g = lane >> 3, li = lane & 7;
    int row = n0 + ((g >> 1) << 3) + li;
    int ch = 2 * s + (g & 1);
    u32 addr = tb + swz(row, ch);
    asm volatile("ldmatrix.sync.aligned.m8n8.x4.shared.b16 {%0,%1,%2,%3}, [%4];"
        : "=r"(r[0]), "=r"(r[1]), "=r"(r[2]), "=r"(r[3]) : "r"(addr));
}

// ============================================================
// HMMA GEMM, one-pass, k=64 chunks, 3-stage cp.async pipeline.
//   C[z] = relu(A[z] @ B[z]^T + bias[z])
// A [M, aK] fp16; B [N, K] fp16 (pre-transposed).
// A k-col for 32-chunk c32 = (c32 & acolmask)*32.  K % 64 == 0, K >= 128.
// 96KB smem -> 2 CTAs/SM.
// mode: 0 = fp32 C, 2 = fp16 C.
// ============================================================
__global__ void __launch_bounds__(256, 2) hmma_t(
    const __half* __restrict__ Ah,
    const __half* __restrict__ Bh, const float* __restrict__ bias,
    float* __restrict__ Cf, __half* __restrict__ Ch,
    int N, int K, int acolmask, int aK,
    size_t sA, size_t sB, size_t sBias, size_t sC, int mode)
{
    extern __shared__ char dsm[];
    const int SUB   = 16384;
    const int STAGE = 2 * SUB;
    const int NSLOT = 4;
    const int tid = threadIdx.x;
    const int wid = tid >> 5;
    const int lane = tid & 31;
    const int z = blockIdx.z;
    const int bm = blockIdx.y << 7;
    const int bn = blockIdx.x << 7;

    Ah += (size_t)z * sA;
    Bh += (size_t)z * sB;  bias += (size_t)z * sBias;

    const u32 sbase = smem_u32(dsm);

    u32 soff[NSLOT];
    const __half* gsrc[NSLOT];
    u32 amask[NSLOT];
    #pragma unroll
    for (int j = 0; j < NSLOT; j++) {
        int sid = tid + (j << 8);
        int buf = sid >> 9;
        int rem = sid & 511;
        int r = rem >> 2;
        int ch = rem & 3;
        soff[j] = (u32)(buf * 8192) + swz(r, ch);
        bool isA = (buf == 0);
        const __half* base = isA ? Ah : Bh;
        int grow = (isA ? bm : bn) + r;
        gsrc[j] = base + (size_t)grow * (isA ? aK : K) + ch * 8;
        amask[j] = isA ? (u32)acolmask : 0xFFFFFFFFu;
    }

    const int nch = K >> 6;   // 64-k chunks

    // prologue: fill stages 0,1
    #pragma unroll
    for (int p = 0; p < 2; p++) {
        u32 sb = sbase + (u32)p * STAGE;
        #pragma unroll
        for (int sc = 0; sc < 2; sc++)
            #pragma unroll
            for (int j = 0; j < NSLOT; j++)
                cpa16(sb + (u32)sc * SUB + soff[j],
                      gsrc[j] + (((u32)(2 * p + sc) & amask[j]) << 5));
        CPA_COMMIT();
    }

    const int wm = (wid & 3) << 5;
    const int wn = (wid >> 2) << 6;
    const u32 Boff = 8192u;

    float acc[2][8][4];
    #pragma unroll
    for (int i = 0; i < 2; i++)
        #pragma unroll
        for (int j = 0; j < 8; j++)
            #pragma unroll
            for (int q = 0; q < 4; q++) acc[i][j][q] = 0.f;

    int stg = 0;   // i % 3
    for (int i = 0; i < nch; i++) {
        CPA_WAIT1();
        __syncthreads();
        int pf = i + 2;
        if (pf < nch) {
            int pstg = stg + 2; if (pstg >= 3) pstg -= 3;
            u32 sb = sbase + (u32)pstg * STAGE;
            #pragma unroll
            for (int sc = 0; sc < 2; sc++)
                #pragma unroll
                for (int j = 0; j < NSLOT; j++)
                    cpa16(sb + (u32)sc * SUB + soff[j],
                          gsrc[j] + (((u32)(2 * pf + sc) & amask[j]) << 5));
        }
        CPA_COMMIT();

        #pragma unroll
        for (int sc = 0; sc < 2; sc++) {
            u32 stb = sbase + (u32)stg * STAGE + (u32)sc * SUB;
            #pragma unroll
            for (int s = 0; s < 2; s++) {
                u32 ah[2][4], b[8][2];
                ldA(stb, wm,      s, ah[0]);
                ldA(stb, wm + 16, s, ah[1]);
                #pragma unroll
                for (int j4 = 0; j4 < 4; j4++) {
                    u32 r[4];
                    ldB(stb + Boff, wn + j4 * 16, s, r);
                    b[2 * j4][0] = r[0]; b[2 * j4][1] = r[1];
                    b[2 * j4 + 1][0] = r[2]; b[2 * j4 + 1][1] = r[3];
                }
                #pragma unroll
                for (int i2 = 0; i2 < 2; i2++)
                    #pragma unroll
                    for (int j8 = 0; j8 < 8; j8++) mma16816(acc[i2][j8], ah[i2], b[j8]);
            }
        }
        if (++stg == 3) stg = 0;
    }

    // epilogue
    const int r0b = bm + wm + (lane >> 2);
    const int c0b = bn + wn + ((lane & 3) << 1);
    #pragma unroll
    for (int i2 = 0; i2 < 2; i2++) {
        #pragma unroll
        for (int j8 = 0; j8 < 8; j8++) {
            int col = c0b + j8 * 8;
            float b0 = bias[col], b1 = bias[col + 1];
            #pragma unroll
            for (int h = 0; h < 2; h++) {
                int row = r0b + i2 * 16 + h * 8;
                float v0 = fmaxf(acc[i2][j8][2 * h]     + b0, 0.f);
                float v1 = fmaxf(acc[i2][j8][2 * h + 1] + b1, 0.f);
                if (mode == 0) {
                    *(float2*)(Cf + (size_t)z * sC + (size_t)row * N + col) = make_float2(v0, v1);
                } else {
                    __half2 hp;
                    hp.x = __float2half_rn(v0);
                    hp.y = __float2half_rn(v1);
                    *(__half2*)(Ch + (size_t)z * sC + (size_t)row * N + col) = hp;
                }
            }
        }
    }
}

// ============================================================
// weight transpose: W[z][K][N] f32 -> T[z][N][K] fp16
// ============================================================
__global__ void transpose_h(const float* __restrict__ W, __half* __restrict__ Th,
                            int Kd, int Nd)
{
    __shared__ float t[32][33];
    int z = blockIdx.z;
    const float* Wz = W + (size_t)z * Kd * Nd;
    int n0 = blockIdx.x << 5, k0 = blockIdx.y << 5;
    for (int r = threadIdx.y; r < 32; r += 8)
        t[r][threadIdx.x] = Wz[(size_t)(k0 + r) * Nd + n0 + threadIdx.x];
    __syncthreads();
    size_t ob = (size_t)z * Nd * Kd;
    for (int r = threadIdx.y; r < 32; r += 8)
        Th[ob + (size_t)(n0 + r) * Kd + k0 + threadIdx.x] = __float2half_rn(t[threadIdx.x][r]);
}

// CE1 collapse: ceW1[z][d*5+p][n] f32 -> CU[z][n][d] = sum_p embB_p*W,
//                                        CU[z][n][512+d] = sum_p embW_p*W
__global__ void prep_cu(const float* __restrict__ W, const float* __restrict__ embW,
                        const float* __restrict__ embB, __half* __restrict__ CU)
{
    __shared__ float t0[32][33], t1[32][33];
    int z = blockIdx.z;
    int n0 = blockIdx.x << 5, d0 = blockIdx.y << 5;
    const float* Wz = W + (size_t)z * KAIT * NH1;
    float ew[PEN], eb[PEN];
    #pragma unroll
    for (int p = 0; p < PEN; p++) { ew[p] = embW[p]; eb[p] = embB[p]; }
    for (int r = threadIdx.y; r < 32; r += 8) {
        float s0 = 0.f, s1 = 0.f;
        #pragma unroll
        for (int p = 0; p < PEN; p++) {
            float w = Wz[(size_t)((d0 + r) * PEN + p) * NH1 + n0 + threadIdx.x];
            s0 += eb[p] * w;
            s1 += ew[p] * w;
        }
        t0[r][threadIdx.x] = s0;
        t1[r][threadIdx.x] = s1;
    }
    __syncthreads();
    size_t ob = (size_t)z * NH1 * 1024;
    for (int r = threadIdx.y; r < 32; r += 8) {
        CU[ob + (size_t)(n0 + r) * 1024 + d0 + threadIdx.x] =
            __float2half_rn(t0[threadIdx.x][r]);
        CU[ob + (size_t)(n0 + r) * 1024 + 512 + d0 + threadIdx.x] =
            __float2half_rn(t1[threadIdx.x][r]);
    }
}

// cgate collapse: u0[d][e] = sum_p embB_p*cgW[d*5+p][e]; u1 likewise with embW
__global__ void prep_ug(const float* __restrict__ cgW, const float* __restrict__ embW,
                        const float* __restrict__ embB, float* __restrict__ u)
{
    int i = blockIdx.x * blockDim.x + threadIdx.x;
    if (i >= DD * 8) return;
    int d = i >> 3, e = i & 7;
    float s0 = 0.f, s1 = 0.f;
    #pragma unroll
    for (int p = 0; p < PEN; p++) {
        float w = cgW[(size_t)(d * PEN + p) * 8 + e];
        s0 += embB[p] * w;
        s1 += embW[p] * w;
    }
    u[i] = s0;
    u[DD * 8 + i] = s1;
}

// elementwise fp32 -> fp16 (hi only)
__global__ void convert_h(const float* __restrict__ src, __half* __restrict__ hi, size_t n)
{
    size_t i = ((size_t)blockIdx.x * blockDim.x + threadIdx.x) * 4;
    if (i >= n) return;
    float4 v = *(const float4*)(src + i);
    __half2 a, b;
    a.x = __float2half_rn(v.x); a.y = __float2half_rn(v.y);
    b.x = __float2half_rn(v.z); b.y = __float2half_rn(v.w);
    *(__half2*)(hi + i) = a; *(__half2*)(hi + i + 2) = b;
}

// cx[b] = [x[b] | pctr[b]*x[b]] fp16 hi only (CE1 A operand), vectorized
__global__ void cx_kernel(const float* __restrict__ x, const float* __restrict__ out,
                          __half* __restrict__ cxh)
{
    int b = blockIdx.x;
    float pc = out[b];
    const float* xr = x + (size_t)b * DD;
    size_t ob = (size_t)b * 1024;
    int d = threadIdx.x * 2;   // 256 threads x 2 = 512
    float2 v = *(const float2*)(xr + d);
    __half2 h0; h0.x = __float2half_rn(v.x); h0.y = __float2half_rn(v.y);
    __half2 h1; h1.x = __float2half_rn(pc * v.x); h1.y = __float2half_rn(pc * v.y);
    *(__half2*)(cxh + ob + d) = h0;
    *(__half2*)(cxh + ob + 512 + d) = h1;
}

// ================= small fp32 kernels =================
__global__ void gates_kernel(const float* __restrict__ x, const float* __restrict__ gW,
                             const float* __restrict__ gb, float* __restrict__ gates)
{
    int gw = (blockIdx.x * blockDim.x + threadIdx.x) >> 5;
    int lane = threadIdx.x & 31;
    if (gw >= NB * 2) return;
    int b = gw >> 1, t = gw & 1;
    const float* xr = x + (size_t)b * DD;
    float acc[8] = {};
    for (int d = lane; d < DD; d += 32) {
        float xv = xr[d];
        const float* g = gW + ((size_t)t * DD + d) * NE;
        float4 w0 = *(const float4*)g;
        float4 w1 = *(const float4*)(g + 4);
        acc[0] += xv * w0.x; acc[1] += xv * w0.y; acc[2] += xv * w0.z; acc[3] += xv * w0.w;
        acc[4] += xv * w1.x; acc[5] += xv * w1.y; acc[6] += xv * w1.z; acc[7] += xv * w1.w;
    }
    #pragma unroll
    for (int e = 0; e < 8; e++)
        #pragma unroll
        for (int o = 16; o; o >>= 1) acc[e] += __shfl_xor_sync(0xffffffffu, acc[e], o);
    float m = -1e30f;
    #pragma unroll
    for (int e = 0; e < 8; e++) { acc[e] += gb[t * 8 + e]; m = fmaxf(m, acc[e]); }
    float s = 0.f;
    #pragma unroll
    for (int e = 0; e < 8; e++) { acc[e] = expf(acc[e] - m); s += acc[e]; }
    float inv = 1.f / s;
    if (lane < 8) gates[((size_t)b * 2 + t) * 8 + lane] = acc[lane] * inv;
}

// fused combine for both tasks + fp16 task_fea (tower input); FEA fp16, vectorized
// Each thread owns 2 consecutive h; per-element accumulation order identical to
// the scalar version (bit-identical results).
__global__ void combine12(const __half* __restrict__ fea, const float* __restrict__ gates,
                          float* __restrict__ o3, float* __restrict__ o4,
                          __half* __restrict__ tfh)
{
    int b = blockIdx.x;
    __shared__ float g[16];
    if (threadIdx.x < 16) g[threadIdx.x] = gates[(size_t)b * 16 + threadIdx.x];
    __syncthreads();
    const __half* f = fea + (size_t)b * NH2;
    int h = threadIdx.x * 2;   // 256 threads x 2 = 512
    float s0a = 0.f, s0b = 0.f, s1a = 0.f, s1b = 0.f;
    #pragma unroll
    for (int e = 0; e < 8; e++) {
        __half2 v2 = *(const __half2*)(f + (size_t)e * NB * NH2 + h);
        float va = __half2float(v2.x);
        float vb = __half2float(v2.y);
        s0a += g[e] * va;      s0b += g[e] * vb;
        s1a += g[8 + e] * va;  s1b += g[8 + e] * vb;
    }
    *(float2*)(o3 + (size_t)b * NH2 + h) = make_float2(s0a, s0b);
    *(float2*)(o4 + (size_t)b * NH2 + h) = make_float2(s1a, s1b);
    __half2 t0; t0.x = __float2half_rn(s0a); t0.y = __float2half_rn(s0b);
    __half2 t1; t1.x = __float2half_rn(s1a); t1.y = __float2half_rn(s1b);
    *(__half2*)(tfh + (size_t)b * NH2 + h) = t0;
    *(__half2*)(tfh + (size_t)(NB + b) * NH2 + h) = t1;
}

// phase-2 combine: ctask -> O5 + fp16 for cascade tower; FEA fp16, vectorized
__global__ void combine1c(const __half* __restrict__ fea, const float* __restrict__ cg,
                          float* __restrict__ o5, __half* __restrict__ cth)
{
    int b = blockIdx.x;
    __shared__ float g[8];
    if (threadIdx.x < 8) g[threadIdx.x] = cg[(size_t)b * 8 + threadIdx.x];
    __syncthreads();
    const __half* f = fea + (size_t)b * NH2;
    int h = threadIdx.x * 2;
    float sa = 0.f, sb = 0.f;
    #pragma unroll
    for (int e = 0; e < 8; e++) {
        __half2 v2 = *(const __half2*)(f + (size_t)e * NB * NH2 + h);
        sa += g[e] * __half2float(v2.x);
        sb += g[e] * __half2float(v2.y);
    }
    *(float2*)(o5 + (size_t)b * NH2 + h) = make_float2(sa, sb);
    __half2 t; t.x = __float2half_rn(sa); t.y = __float2half_rn(sb);
    *(__half2*)(cth + (size_t)b * NH2 + h) = t;
}

__global__ void preds_kernel(const float* __restrict__ outr, const float* __restrict__ pW,
                             const float* __restrict__ pb, float* __restrict__ out)
{
    int gw = (blockIdx.x * blockDim.x + threadIdx.x) >> 5;
    int lane = threadIdx.x & 31;
    if (gw >= NB * 2) return;
    int b = gw >> 1, t = gw & 1;
    const float* th2 = outr + O6 + (size_t)t * NB * TT2 + (size_t)b * TT2;
    const float* w = pW + t * TT2;
    float s = 0.f;
    for (int m = lane; m < TT2; m += 32) s += th2[m] * w[m];
    #pragma unroll
    for (int o = 16; o; o >>= 1) s += __shfl_xor_sync(0xffffffffu, s, o);
    if (lane == 0) {
        s += pb[t];
        out[(size_t)t * NB + b] = 1.f / (1.f + expf(-s));
    }
}

// cgate via collapsed u: logits_e = x.u0[:,e] + pctr*(x.u1[:,e]) + cgb
__global__ void cgate_kernel(const float* __restrict__ x, const float* __restrict__ out,
                             const float* __restrict__ u, const float* __restrict__ cgb,
                             float* __restrict__ cg)
{
    int gw = (blockIdx.x * blockDim.x + threadIdx.x) >> 5;
    int lane = threadIdx.x & 31;
    if (gw >= NB) return;
    const float* xr = x + (size_t)gw * DD;
    float a0[8] = {}, a1[8] = {};
    for (int d = lane; d < DD; d += 32) {
        float xv = xr[d];
        const float* u0 = u + (size_t)d * 8;
        const float* u1 = u + (size_t)(DD + d) * 8;
        float4 w0 = *(const float4*)u0;
        float4 w1 = *(const float4*)(u0 + 4);
        a0[0] += xv * w0.x; a0[1] += xv * w0.y; a0[2] += xv * w0.z; a0[3] += xv * w0.w;
        a0[4] += xv * w1.x; a0[5] += xv * w1.y; a0[6] += xv * w1.z; a0[7] += xv * w1.w;
        float4 v0 = *(const float4*)u1;
        float4 v1 = *(const float4*)(u1 + 4);
        a1[0] += xv * v0.x; a1[1] += xv * v0.y; a1[2] += xv * v0.z; a1[3] += xv * v0.w;
        a1[4] += xv * v1.x; a1[5] += xv * v1.y; a1[6] += xv * v1.z; a1[7] += xv * v1.w;
    }
    #pragma unroll
    for (int e = 0; e < 8; e++) {
        #pragma unroll
        for (int o = 16; o; o >>= 1) {
            a0[e] += __shfl_xor_sync(0xffffffffu, a0[e], o);
            a1[e] += __shfl_xor_sync(0xffffffffu, a1[e], o);
        }
    }
    float pc = out[gw];
    float m = -1e30f;
    float acc[8];
    #pragma unroll
    for (int e = 0; e < 8; e++) {
        acc[e] = a0[e] + pc * a1[e] + cgb[e];
        m = fmaxf(m, acc[e]);
    }
    float s = 0.f;
    #pragma unroll
    for (int e = 0; e < 8; e++) { acc[e] = expf(acc[e] - m); s += acc[e]; }
    float inv = 1.f / s;
    if (lane < 8) cg[(size_t)gw * 8 + lane] = acc[lane] * inv;
}

__global__ void pconv_kernel(const float* __restrict__ outr, const float* __restrict__ cpW,
                             const float* __restrict__ cpb, float* __restrict__ out)
{
    int gw = (blockIdx.x * blockDim.x + threadIdx.x) >> 5;
    int lane = threadIdx.x & 31;
    if (gw >= NB) return;
    const float* ch2 = outr + O8 + (size_t)gw * TT2;
    float s = 0.f;
    for (int m = lane; m < TT2; m += 32) s += ch2[m] * cpW[m];
    #pragma unroll
    for (int o = 16; o; o >>= 1) s += __shfl_xor_sync(0xffffffffu, s, o);
    if (lane == 0) out[O2 + gw] = 1.f / (1.f + expf(-(s + cpb[0])));
}

// ============================================================
extern "C" void kernel_launch(void* const* d_in, const int* in_sizes, int n_in,
                              void* d_out, int out_size)
{
    const float* x    = (const float*)d_in[0];
    const float* eW1  = (const float*)d_in[1];
    const float* eb1  = (const float*)d_in[2];
    const float* eW2  = (const float*)d_in[3];
    const float* eb2  = (const float*)d_in[4];
    const float* gW   = (const float*)d_in[5];
    const float* gb   = (const float*)d_in[6];
    const float* tW1  = (const float*)d_in[7];
    const float* tb1  = (const float*)d_in[8];
    const float* tW2  = (const float*)d_in[9];
    const float* tb2  = (const float*)d_in[10];
    const float* pW   = (const float*)d_in[11];
    const float* pb   = (const float*)d_in[12];
    const float* embW = (const float*)d_in[13];
    const float* embB = (const float*)d_in[14];
    const float* ceW1 = (const float*)d_in[15];
    const float* ceb1 = (const float*)d_in[16];
    const float* ceW2 = (const float*)d_in[17];
    const float* ceb2 = (const float*)d_in[18];
    const float* cgW  = (const float*)d_in[19];
    const float* cgb  = (const float*)d_in[20];
    const float* ctW1 = (const float*)d_in[21];
    const float* ctb1 = (const float*)d_in[22];
    const float* ctW2 = (const float*)d_in[23];
    const float* ctb2 = (const float*)d_in[24];
    const float* cpW  = (const float*)d_in[25];
    const float* cpb  = (const float*)d_in[26];
    float* out = (float*)d_out;

    __half *xh, *cxh, *Hh, *FEAh, *W1h, *W2h, *CUh, *CW2h, *tW1h, *tW2h, *cW1h, *cW2h;
    __half *tfh, *th1h, *cth, *ch1h;
    float *pG, *pCG, *pUG;
    cudaGetSymbolAddress((void**)&xh, g_xh);
    cudaGetSymbolAddress((void**)&cxh, g_cxh);
    cudaGetSymbolAddress((void**)&Hh, g_Hh);
    cudaGetSymbolAddress((void**)&FEAh, g_FEAh);
    cudaGetSymbolAddress((void**)&W1h, g_W1h); cudaGetSymbolAddress((void**)&W2h, g_W2h);
    cudaGetSymbolAddress((void**)&CUh, g_CUh); cudaGetSymbolAddress((void**)&CW2h, g_CW2h);
    cudaGetSymbolAddress((void**)&tW1h, g_tW1h); cudaGetSymbolAddress((void**)&tW2h, g_tW2h);
    cudaGetSymbolAddress((void**)&cW1h, g_cW1h); cudaGetSymbolAddress((void**)&cW2h, g_cW2h);
    cudaGetSymbolAddress((void**)&tfh, g_tfh);
    cudaGetSymbolAddress((void**)&th1h, g_th1h);
    cudaGetSymbolAddress((void**)&cth, g_cth);
    cudaGetSymbolAddress((void**)&ch1h, g_ch1h);
    cudaGetSymbolAddress((void**)&pG, g_GATES);
    cudaGetSymbolAddress((void**)&pCG, g_CGATE);
    cudaGetSymbolAddress((void**)&pUG, g_UG);

    const int SM1 = 3 * 2 * 16384;   // 98304, 2 CTAs/SM
    cudaFuncSetAttribute(hmma_t, cudaFuncAttributeMaxDynamicSharedMemorySize, SM1);
    dim3 blk(256);
    dim3 tb(32, 8);

    // ---- side stream + fork/join events (created once; host-side only) ----
    static cudaStream_t s2 = nullptr;
    static cudaEvent_t evFork = nullptr, evPrep = nullptr, evPred = nullptr, evCg = nullptr;
    if (s2 == nullptr) {
        cudaStreamCreateWithFlags(&s2, cudaStreamNonBlocking);
        cudaEventCreateWithFlags(&evFork, cudaEventDisableTiming);
        cudaEventCreateWithFlags(&evPrep, cudaEventDisableTiming);
        cudaEventCreateWithFlags(&evPred, cudaEventDisableTiming);
        cudaEventCreateWithFlags(&evCg,   cudaEventDisableTiming);
    }

    // fork s2 from the main (legacy) stream
    cudaEventRecord(evFork, 0);
    cudaStreamWaitEvent(s2, evFork, 0);

    // ---- side stream: all prep not needed for E1, plus gates ----
    transpose_h<<<dim3(NH2 / 32, NH1 / 32, NE), tb, 0, s2>>>(eW2, W2h, NH1, NH2);
    prep_cu<<<dim3(NH1 / 32, DD / 32, NE), tb, 0, s2>>>(ceW1, embW, embB, CUh);
    transpose_h<<<dim3(NH2 / 32, NH1 / 32, NE), tb, 0, s2>>>(ceW2, CW2h, NH1, NH2);
    transpose_h<<<dim3(TT1 / 32, NH2 / 32, 2), tb, 0, s2>>>(tW1, tW1h, NH2, TT1);
    transpose_h<<<dim3(TT2 / 32, TT1 / 32, 2), tb, 0, s2>>>(tW2, tW2h, TT1, TT2);
    transpose_h<<<dim3(TT1 / 32, NH2 / 32, 1), tb, 0, s2>>>(ctW1, cW1h, NH2, TT1);
    transpose_h<<<dim3(TT2 / 32, TT1 / 32, 1), tb, 0, s2>>>(ctW2, cW2h, TT1, TT2);
    prep_ug<<<(DD * 8 + 255) / 256, 256, 0, s2>>>(cgW, embW, embB, pUG);
    gates_kernel<<<NB * 2 / 8, 256, 0, s2>>>(x, gW, gb, pG);
    cudaEventRecord(evPrep, s2);

    // ---- main stream: critical path ----
    transpose_h<<<dim3(NH1 / 32, DD / 32, NE), tb>>>(eW1, W1h, DD, NH1);
    convert_h<<<NB * DD / 4 / 256, 256>>>(x, xh, (size_t)NB * DD);

    hmma_t<<<dim3(NH1 / 128, NB / 128, NE), blk, SM1>>>(
        xh, W1h, eb1, nullptr, Hh,
        NH1, DD, 15, DD, 0, (size_t)NH1 * DD, NH1, (size_t)NB * NH1, 2);

    // join: E2 and everything after need W2h/gates/CUh/... from s2
    cudaStreamWaitEvent(0, evPrep, 0);

    hmma_t<<<dim3(NH2 / 128, NB / 128, NE), blk, SM1>>>(
        Hh, W2h, eb2, nullptr, FEAh,
        NH2, NH1, 31, NH1, (size_t)NB * NH1, (size_t)NH2 * NH1, NH2, (size_t)NB * NH2, 2);

    combine12<<<NB, 256>>>(FEAh, pG, out + O3, out + O4, tfh);

    // towers (one-pass, 2 CTAs/SM)
    hmma_t<<<dim3(TT1 / 128, NB / 128, 2), blk, SM1>>>(
        tfh, tW1h, tb1, nullptr, th1h,
        TT1, NH2, 15, NH2, (size_t)NB * NH2, (size_t)TT1 * NH2, TT1, (size_t)NB * TT1, 2);
    hmma_t<<<dim3(1, NB / 128, 2), blk, SM1>>>(
        th1h, tW2h, tb2, out + O6, nullptr,
        TT2, TT1, 7, TT1, (size_t)NB * TT1, (size_t)TT2 * TT1, TT2, (size_t)NB * TT2, 0);
    preds_kernel<<<NB * 2 / 8, 256>>>(out, pW, pb, out);

    // fork: cgate on s2 (needs pctr + UG), concurrent with cx/CE1/CE2
    cudaEventRecord(evPred, 0);
    cudaStreamWaitEvent(s2, evPred, 0);
    cgate_kernel<<<NB / 8, 256, 0, s2>>>(x, out, pUG, cgb, pCG);
    cudaEventRecord(evCg, s2);

    // ---- phase 2 on main stream ----
    cx_kernel<<<NB, 256>>>(x, out, cxh);
    hmma_t<<<dim3(NH1 / 128, NB / 128, NE), blk, SM1>>>(
        cxh, CUh, ceb1, nullptr, Hh,
        NH1, 1024, 31, 1024, 0, (size_t)NH1 * 1024, NH1, (size_t)NB * NH1, 2);
    hmma_t<<<dim3(NH2 / 128, NB / 128, NE), blk, SM1>>>(
        Hh, CW2h, ceb2, nullptr, FEAh,
        NH2, NH1, 31, NH1, (size_t)NB * NH1, (size_t)NH2 * NH1, NH2, (size_t)NB * NH2, 2);

    // join cgate before combine1c
    cudaStreamWaitEvent(0, evCg, 0);
    combine1c<<<NB, 256>>>(FEAh, pCG, out + O5, cth);

    hmma_t<<<dim3(TT1 / 128, NB / 128, 1), blk, SM1>>>(
        cth, cW1h, ctb1, nullptr, ch1h,
        TT1, NH2, 15, NH2, 0, 0, 0, (size_t)NB * TT1, 2);
    hmma_t<<<dim3(1, NB / 128, 1), blk, SM1>>>(
        ch1h, cW2h, ctb2, out + O8, nullptr,
        TT2, TT1, 7, TT1, 0, 0, 0, 0, 0);
    pconv_kernel<<<NB / 8, 256>>>(out, cpW, cpb, out);
}